// round 16
// baseline (speedup 1.0000x reference)
#include <cuda_runtime.h>
#include <cuda_fp16.h>
#include <cstdint>

// out[N,128] = [ self_x@Ws + bs , ((adj@nx)/deg)@Wn + bn ]
// Single fused GEMM kernel: C = adj @ nx^T-layout via fp16 mma.sync m16n8k16
// (fallback HMMA; tcgen05 unavailable on this toolchain), deg computed during
// the in-smem fp32->fp16 convert, and BOTH 64x64 linear layers fused into a
// fp32 FFMA epilogue writing d_out directly. No g_AGG, no finalize kernel.

#define Nn 16384
#define Kk 16384
#define BM 64
#define KT 32
#define NKT (Kk / KT)       // 512
#define NSTAGE 4

// ---- smem layout (bytes) ----
// mainloop: Araw fp32 4 stages | B fp16 4 stages | Amm fp16 2 bufs | degs
#define ARAW_STF 2048        // f32 per A stage (64 rows x 32)
#define BST_STU  1536        // u32 per B stage (64 rows x 24; 16 data + 8 pad)
#define AMM_STU  1280        // u32 per Amm buf (64 rows x 20; 16 data + 4 pad)
#define OFF_B    32768
#define OFF_AM   57344
#define OFF_DEG  67584
#define DSMEM    68096
// epilogue (reuses mainloop regions; DEGS preserved):
#define OFF_SXA  0           // AGG rows   [64][68] f32
#define OFF_SXS  17408       // self_x     [64][68] f32
#define OFF_WSS  34816       // Ws fp32    [64][64]
#define OFF_WNN  51200       // Wn fp32    [64][64]

__device__ __half g_X2Th[64 * Kk];   // nx^T fp16, K-major rows, pair-permuted u32s

__device__ __forceinline__ void cp16(void* s, const void* g) {
    uint32_t sa = (uint32_t)__cvta_generic_to_shared(s);
    asm volatile("cp.async.cg.shared.global [%0], [%1], 16;" :: "r"(sa), "l"(g));
}
__device__ __forceinline__ void cp_commit() { asm volatile("cp.async.commit_group;"); }
__device__ __forceinline__ void cp_wait2()  { asm volatile("cp.async.wait_group 2;"); }
__device__ __forceinline__ void cp_wait0()  { asm volatile("cp.async.wait_group 0;"); }

__device__ __forceinline__ void ldsm4(uint32_t* r, uint32_t saddr) {
    asm volatile("ldmatrix.sync.aligned.m8n8.x4.shared.b16 {%0,%1,%2,%3}, [%4];"
                 : "=r"(r[0]), "=r"(r[1]), "=r"(r[2]), "=r"(r[3]) : "r"(saddr));
}
__device__ __forceinline__ void mma16816(float* c, const uint32_t* a, uint32_t b0, uint32_t b1) {
    asm volatile("mma.sync.aligned.m16n8k16.row.col.f32.f16.f16.f32 "
                 "{%0,%1,%2,%3}, {%4,%5,%6,%7}, {%8,%9}, {%0,%1,%2,%3};"
                 : "+f"(c[0]), "+f"(c[1]), "+f"(c[2]), "+f"(c[3])
                 : "r"(a[0]), "r"(a[1]), "r"(a[2]), "r"(a[3]), "r"(b0), "r"(b1));
}

// ---------------------------------------------------------------------------
// prep: nx[16384,64] fp32 -> g_X2Th (transposed, fp16, u32 pair-permuted so
// the two m16n8k16 B-frag pairs {t4,t4+4},{t4+8,t4+12} are LDS.64-contiguous)
// ---------------------------------------------------------------------------
__global__ __launch_bounds__(256) void prep_t(const float* __restrict__ nx) {
    __shared__ float t[64][65];
    const int kb = blockIdx.x * 64;
#pragma unroll
    for (int i = 0; i < 16; i++) {
        int id = threadIdx.x + 256 * i;
        int k = id >> 6, n = id & 63;
        t[k][n] = nx[(size_t)(kb + k) * 64 + n];
    }
    __syncthreads();
#pragma unroll
    for (int i = 0; i < 16; i++) {
        int id = threadIdx.x + 256 * i;
        int n = id >> 6, k = id & 63;
        int kg = kb + k;
        int o = (kg & 31) >> 1;                          // u32 index within 32-k block
        int p = (o >> 3) * 8 + (o & 3) * 2 + ((o & 7) >> 2);
        size_t idx = (size_t)n * Kk + (size_t)(kg >> 5) * 32 + p * 2 + (kg & 1);
        g_X2Th[idx] = __float2half_rn(t[k][n]);
    }
}

// ---------------------------------------------------------------------------
// fused GEMM + epilogue
// ---------------------------------------------------------------------------
__global__ __launch_bounds__(256, 2) void agg_gemm(
    const float* __restrict__ adj, const float* __restrict__ self_x,
    const float* __restrict__ Ws, const float* __restrict__ Wn,
    const float* __restrict__ bs, const float* __restrict__ bn,
    float* __restrict__ out)
{
    extern __shared__ char smem[];
    float*    Araw = (float*)smem;
    uint32_t* Bst  = (uint32_t*)(smem + OFF_B);
    uint32_t* Amm  = (uint32_t*)(smem + OFF_AM);
    float*    degs = (float*)(smem + OFF_DEG);
    const uint32_t amm_s = (uint32_t)__cvta_generic_to_shared(Amm);

    const int tid  = threadIdx.x;
    const int lane = tid & 31;
    const int w    = tid >> 5;          // 0..7
    const int g    = w >> 2;            // n-group: 0 -> cols 0..31, 1 -> 32..63
    const int wm   = (w & 3) * 16;      // m-rows base for MMA
    const int t4   = lane & 3;
    const int row0 = blockIdx.x * BM;
    const float* gA0 = adj + (size_t)row0 * Kk;

    float c[4][4];
#pragma unroll
    for (int i = 0; i < 4; i++) { c[i][0] = c[i][1] = c[i][2] = c[i][3] = 0.f; }
    float ds0 = 0.f, ds1 = 0.f;         // degree partials (rows cvr0 / cvr0+4)
    const int cvr0 = w * 8 + (lane >> 3);        // convert row (i=0)
    const int cvc  = (lane & 7) * 4;             // convert col base

    auto load_stage = [&](int st, int kt) {
        const float* ga = gA0 + kt * KT;
        float* da = Araw + st * ARAW_STF;
#pragma unroll
        for (int i = 0; i < 2; i++) {            // A: 64 rows x 128B = 512 chunks
            int id = tid + 256 * i;
            int m = id >> 3, kg = id & 7;
            cp16(da + m * 32 + kg * 4, ga + (size_t)m * Kk + kg * 4);
        }
        // B: 64 rows x 64B = 256 chunks (one per thread)
        int n = tid >> 2, ch = tid & 3;
        cp16(Bst + st * BST_STU + n * 24 + ch * 4,
             g_X2Th + (size_t)n * Kk + kt * 32 + ch * 8);
    };

    for (int s = 0; s < NSTAGE - 1; s++) { load_stage(s, s); cp_commit(); }

    for (int kt = 0; kt < NKT; kt++) {
        const int st = kt & 3;
        cp_wait2();
        __syncthreads();

        // convert 8 rows per warp: fp32 -> fp16 (Amm), accumulate degree in fp32
        {
            const float* src = Araw + st * ARAW_STF;
            uint32_t* dst = Amm + (kt & 1) * AMM_STU;
            float4 v0 = *(const float4*)(src + cvr0 * 32 + cvc);
            float4 v1 = *(const float4*)(src + (cvr0 + 4) * 32 + cvc);
            ds0 += (v0.x + v0.y) + (v0.z + v0.w);
            ds1 += (v1.x + v1.y) + (v1.z + v1.w);
            __half2 h00 = __floats2half2_rn(v0.x, v0.y), h01 = __floats2half2_rn(v0.z, v0.w);
            __half2 h10 = __floats2half2_rn(v1.x, v1.y), h11 = __floats2half2_rn(v1.z, v1.w);
            *(uint2*)(dst + cvr0 * 20 + (lane & 7) * 2) =
                make_uint2(*(uint32_t*)&h00, *(uint32_t*)&h01);
            *(uint2*)(dst + (cvr0 + 4) * 20 + (lane & 7) * 2) =
                make_uint2(*(uint32_t*)&h10, *(uint32_t*)&h11);
        }
        __syncthreads();

        const int nxt = kt + NSTAGE - 1;
        if (nxt < NKT) load_stage(nxt & 3, nxt);
        cp_commit();

        // A fragments via ldmatrix.x4 (two k16 tiles)
        uint32_t a0[4], a1[4];
        {
            uint32_t r = wm + (lane & 7) + ((lane >> 3) & 1) * 8;
            uint32_t ad = amm_s + ((kt & 1) * AMM_STU + r * 20 + ((lane >> 4) & 1) * 4) * 4;
            ldsm4(a0, ad);
            ldsm4(a1, ad + 32);
        }
        const uint32_t* bstp = Bst + st * BST_STU;
#pragma unroll
        for (int nt = 0; nt < 4; nt++) {
            const uint32_t* bp = bstp + ((g * 4 + nt) * 8 + (lane >> 2)) * 24;
            uint2 B0 = *(const uint2*)(bp + 2 * t4);
            uint2 B1 = *(const uint2*)(bp + 8 + 2 * t4);
            mma16816(c[nt], a0, B0.x, B0.y);
            mma16816(c[nt], a1, B1.x, B1.y);
        }
    }

    // ---------------- epilogue ----------------
    cp_wait0();
    __syncthreads();

    // reduce degree partials across the 8 lanes sharing each row
    ds0 += __shfl_xor_sync(0xffffffffu, ds0, 1);
    ds0 += __shfl_xor_sync(0xffffffffu, ds0, 2);
    ds0 += __shfl_xor_sync(0xffffffffu, ds0, 4);
    ds1 += __shfl_xor_sync(0xffffffffu, ds1, 1);
    ds1 += __shfl_xor_sync(0xffffffffu, ds1, 2);
    ds1 += __shfl_xor_sync(0xffffffffu, ds1, 4);
    if ((lane & 7) == 0) { degs[cvr0] = ds0; degs[cvr0 + 4] = ds1; }
    __syncthreads();

    // stage self_x + Ws + Wn (fp32) while we unload accumulators
    float* SXA = (float*)(smem + OFF_SXA);
    float* SXS = (float*)(smem + OFF_SXS);
    float* WSS = (float*)(smem + OFF_WSS);
    float* WNN = (float*)(smem + OFF_WNN);
#pragma unroll
    for (int i = 0; i < 4; i++) {
        int id = tid + 256 * i;
        int r = id >> 4, ch = id & 15;
        cp16(SXS + r * 68 + ch * 4, self_x + (size_t)(row0 + r) * 64 + ch * 4);
        cp16(WSS + r * 64 + ch * 4, Ws + (size_t)r * 64 + ch * 4);
        cp16(WNN + r * 64 + ch * 4, Wn + (size_t)r * 64 + ch * 4);
    }
    cp_commit();

    // accumulators -> SXA with deg normalization
    {
        const int m0 = wm + (lane >> 2);
        const float i0 = 1.f / fmaxf(degs[m0], 1.f);
        const float i1 = 1.f / fmaxf(degs[m0 + 8], 1.f);
#pragma unroll
        for (int nt = 0; nt < 4; nt++) {
            int col = g * 32 + nt * 8 + 2 * t4;
            *(float2*)(SXA + m0 * 68 + col)       = make_float2(c[nt][0] * i0, c[nt][1] * i0);
            *(float2*)(SXA + (m0 + 8) * 68 + col) = make_float2(c[nt][2] * i1, c[nt][3] * i1);
        }
    }
    cp_wait0();
    __syncthreads();

    // fp32 FFMA: thread (r, q): q0 self cols 0-31, q1 self 32-63, q2 neigh 0-31, q3 neigh 32-63
    {
        const int r = tid >> 2, q = tid & 3;
        const float* src = (q < 2 ? SXS : SXA) + r * 68;
        const float* Wp  = (q < 2 ? WSS : WNN) + (q & 1) * 32;
        float acc[32];
#pragma unroll
        for (int j = 0; j < 32; j++) acc[j] = 0.f;
#pragma unroll 4
        for (int k = 0; k < 64; k++) {
            float v = src[k];
            const float* wr = Wp + k * 64;
#pragma unroll
            for (int j = 0; j < 8; j++) {
                float4 ww = *(const float4*)(wr + j * 4);
                acc[4*j]   += v * ww.x; acc[4*j+1] += v * ww.y;
                acc[4*j+2] += v * ww.z; acc[4*j+3] += v * ww.w;
            }
        }
        const float* bias = (q < 2 ? bs : bn) + (q & 1) * 32;
        float* dst = out + (size_t)(row0 + r) * 128 + (q >> 1) * 64 + (q & 1) * 32;
#pragma unroll
        for (int j = 0; j < 8; j++) {
            float4 b = *(const float4*)(bias + j * 4);
            *(float4*)(dst + j * 4) = make_float4(acc[4*j] + b.x, acc[4*j+1] + b.y,
                                                  acc[4*j+2] + b.z, acc[4*j+3] + b.w);
        }
    }
}

// ---------------------------------------------------------------------------
extern "C" void kernel_launch(void* const* d_in, const int* in_sizes, int n_in,
                              void* d_out, int out_size)
{
    const float* self_x     = (const float*)d_in[0];
    const float* neighbor_x = (const float*)d_in[1];
    const float* adj        = (const float*)d_in[2];
    const float* Ws         = (const float*)d_in[3];
    const float* Wn         = (const float*)d_in[4];
    const float* bs         = (const float*)d_in[5];
    const float* bn         = (const float*)d_in[6];
    float* out = (float*)d_out;

    cudaFuncSetAttribute(agg_gemm, cudaFuncAttributeMaxDynamicSharedMemorySize, DSMEM);

    prep_t<<<Kk / 64, 256>>>(neighbor_x);
    agg_gemm<<<Nn / BM, 256, DSMEM>>>(adj, self_x, Ws, Wn, bs, bn, out);
}

// round 17
// speedup vs baseline: 1.0269x; 1.0269x over previous
#include <cuda_runtime.h>
#include <cuda_fp16.h>
#include <cstdint>

// out[N,128] = [ self_x@Ws + bs , ((adj@nx)/deg)@Wn + bn ]
// R9: barrier-free mainloop. 4 decoupled warps per CTA; each warp owns 16 rows
// x all 64 cols. A: warp-private 8-stage cp.async ring + in-register fp32->fp16
// convert (LDS.64 -> cvt = a-frags; degree from same values). B: fragment-major
// global layout, LDG.128 from L2 with 1-iter register prefetch. No smem B, no
// ldmatrix, no __syncthreads until the fused fp32 epilogue.

#define Nn 16384
#define Kk 16384
#define BM 64
#define KT 32
#define NKT (Kk / KT)        // 512
#define NST 8                // cp.async stages (warp-private, 2KB each)

// epilogue smem layout (reuses the mainloop A region, 64KB)
#define OFF_SXA 0            // AGG rows [64][68] f32
#define OFF_SXS 17408        // self_x   [64][68] f32
#define OFF_WSS 34816        // Ws       [64][64] f32
#define OFF_WNN 51200        // Wn       [64][64] f32
#define DSMEM   67584

// B fragments, fragment-major: u32 idx = kt*1024 + c*128 + lane*4 + j
// (c = n-pair/ktile chunk; one uint4 per (lane, c); +1 kt of padding for the
//  final prefetch)
__device__ uint4 g_B[(NKT + 1) * 256];

__device__ __forceinline__ void cp16(void* s, const void* g) {
    uint32_t sa = (uint32_t)__cvta_generic_to_shared(s);
    asm volatile("cp.async.cg.shared.global [%0], [%1], 16;" :: "r"(sa), "l"(g));
}
__device__ __forceinline__ void cp_commit() { asm volatile("cp.async.commit_group;"); }
__device__ __forceinline__ void cp_wait6()  { asm volatile("cp.async.wait_group 6;"); }
__device__ __forceinline__ void cp_wait0()  { asm volatile("cp.async.wait_group 0;"); }

__device__ __forceinline__ void mma16816(float* c, const uint32_t* a, uint32_t b0, uint32_t b1) {
    asm volatile("mma.sync.aligned.m16n8k16.row.col.f32.f16.f16.f32 "
                 "{%0,%1,%2,%3}, {%4,%5,%6,%7}, {%8,%9}, {%0,%1,%2,%3};"
                 : "+f"(c[0]), "+f"(c[1]), "+f"(c[2]), "+f"(c[3])
                 : "r"(a[0]), "r"(a[1]), "r"(a[2]), "r"(a[3]), "r"(b0), "r"(b1));
}

// ---------------------------------------------------------------------------
// prep: nx[16384,64] fp32 -> g_B fragment-major fp16.
// For k-slice kt: chunk c (0..7): ktile = c&1, n-pair = c>>1; lane l, word j:
//   nt = (c>>1)*2 + (j>>1), n = nt*8 + (l>>2),
//   k = (c&1)*16 + 2*(l&3) + (j&1)*8  -> u32 = half2(B[k][n], B[k+1][n])
// ---------------------------------------------------------------------------
__global__ __launch_bounds__(256) void prep_b(const float* __restrict__ nx) {
    __shared__ float sm[32 * 64];
    const int kt = blockIdx.x;
#pragma unroll
    for (int i = 0; i < 8; i++) {
        int id = threadIdx.x + 256 * i;          // 2048 floats
        sm[id] = nx[(size_t)kt * 32 * 64 + id];  // sm[k][n], k stride 64
    }
    __syncthreads();
    uint32_t* gb = (uint32_t*)g_B + (size_t)kt * 1024;
#pragma unroll
    for (int i = 0; i < 4; i++) {
        int id = threadIdx.x + 256 * i;          // 1024 u32
        int c = id >> 7, l = (id >> 2) & 31, j = id & 3;
        int nt = ((c >> 1) << 1) + (j >> 1);
        int n  = nt * 8 + (l >> 2);
        int k  = (c & 1) * 16 + 2 * (l & 3) + (j & 1) * 8;
        __half2 h = __floats2half2_rn(sm[k * 64 + n], sm[(k + 1) * 64 + n]);
        gb[id] = *(uint32_t*)&h;
    }
}

// ---------------------------------------------------------------------------
// fused GEMM + epilogue
// ---------------------------------------------------------------------------
__global__ __launch_bounds__(128) void agg_gemm(
    const float* __restrict__ adj, const float* __restrict__ self_x,
    const float* __restrict__ Ws, const float* __restrict__ Wn,
    const float* __restrict__ bs, const float* __restrict__ bn,
    float* __restrict__ out)
{
    extern __shared__ char smem[];
    const int tid  = threadIdx.x;
    const int lane = tid & 31;
    const int w    = tid >> 5;           // 0..3
    const int t4   = lane & 3;
    const int rl   = lane >> 2;          // 0..7
    const int row0 = blockIdx.x * BM;

    char* Aw = smem + w * (NST * 2048);  // warp-private A ring
    const float* gA = adj + (size_t)(row0 + w * 16) * Kk;

    float acc[8][4];
#pragma unroll
    for (int i = 0; i < 8; i++) { acc[i][0] = acc[i][1] = acc[i][2] = acc[i][3] = 0.f; }
    float ds0 = 0.f, ds1 = 0.f;          // degree partials for rows rl / rl+8

    auto loadA = [&](int kt) {           // warp-private: 16 rows x 128B, swizzled
        char* dst = Aw + (kt & 7) * 2048;
#pragma unroll
        for (int i = 0; i < 4; i++) {
            int id = lane + 32 * i;
            int r = id >> 3, ch = id & 7;
            cp16(dst + r * 128 + ((ch ^ (r & 7)) << 4),
                 gA + (size_t)r * Kk + kt * KT + ch * 4);
        }
    };

#pragma unroll
    for (int s = 0; s < NST - 1; s++) { loadA(s); cp_commit(); }

    const uint4* gBl = g_B + lane;       // + kt*256 + c*32
    uint4 br[2][8];
#pragma unroll
    for (int c = 0; c < 8; c++) br[0][c] = gBl[c * 32];

    auto body = [&](int kt, uint4* bc, uint4* bnx) {
        cp_wait6();
        __syncwarp();
        // prefetch next-iter B fragments (L2-resident)
#pragma unroll
        for (int c = 0; c < 8; c++) bnx[c] = gBl[(size_t)(kt + 1) * 256 + c * 32];

        // a-frags: swizzled LDS.64 of fp32 pairs -> cvt (+ degree in fp32)
        const char* sb = Aw + (kt & 7) * 2048;
        uint32_t af[2][4];
#pragma unroll
        for (int k2 = 0; k2 < 2; k2++) {
            const int cb0 = k2 * 64 + 8 * t4;   // byte col of k = k2*16 + 2*t4
            const int cb1 = cb0 + 32;           // k + 8
            const int s0 = (((cb0 >> 4) ^ rl) << 4) + (cb0 & 15);
            const int s1 = (((cb1 >> 4) ^ rl) << 4) + (cb1 & 15);
            float2 L0 = *(const float2*)(sb + rl * 128 + s0);
            float2 L1 = *(const float2*)(sb + (rl + 8) * 128 + s0);
            float2 L2 = *(const float2*)(sb + rl * 128 + s1);
            float2 L3 = *(const float2*)(sb + (rl + 8) * 128 + s1);
            ds0 += (L0.x + L0.y) + (L2.x + L2.y);
            ds1 += (L1.x + L1.y) + (L3.x + L3.y);
            __half2 h;
            h = __floats2half2_rn(L0.x, L0.y); af[k2][0] = *(uint32_t*)&h;
            h = __floats2half2_rn(L1.x, L1.y); af[k2][1] = *(uint32_t*)&h;
            h = __floats2half2_rn(L2.x, L2.y); af[k2][2] = *(uint32_t*)&h;
            h = __floats2half2_rn(L3.x, L3.y); af[k2][3] = *(uint32_t*)&h;
        }

        if (kt + NST - 1 < NKT) loadA(kt + NST - 1);
        cp_commit();                      // unconditional: uniform group count

#pragma unroll
        for (int c = 0; c < 8; c++) {     // 16 MMAs: c = (n-pair)*2 + ktile
            const int k2 = c & 1, np = c >> 1;
            mma16816(acc[np * 2],     af[k2], bc[c].x, bc[c].y);
            mma16816(acc[np * 2 + 1], af[k2], bc[c].z, bc[c].w);
        }
    };

    for (int kt = 0; kt < NKT; kt += 2) {
        body(kt,     br[0], br[1]);
        body(kt + 1, br[1], br[0]);
    }

    // ---------------- epilogue ----------------
    // degree: reduce across the 4 lanes (t4) sharing each row
    ds0 += __shfl_xor_sync(0xffffffffu, ds0, 1);
    ds0 += __shfl_xor_sync(0xffffffffu, ds0, 2);
    ds1 += __shfl_xor_sync(0xffffffffu, ds1, 1);
    ds1 += __shfl_xor_sync(0xffffffffu, ds1, 2);

    __syncthreads();                      // all warps done with A ring

    float* SXA = (float*)(smem + OFF_SXA);
    float* SXS = (float*)(smem + OFF_SXS);
    float* WSS = (float*)(smem + OFF_WSS);
    float* WNN = (float*)(smem + OFF_WNN);
#pragma unroll
    for (int i = 0; i < 8; i++) {
        int id = tid + 128 * i;
        int r = id >> 4, ch = id & 15;
        cp16(SXS + r * 68 + ch * 4, self_x + (size_t)(row0 + r) * 64 + ch * 4);
        cp16(WSS + r * 64 + ch * 4, Ws + (size_t)r * 64 + ch * 4);
        cp16(WNN + r * 64 + ch * 4, Wn + (size_t)r * 64 + ch * 4);
    }
    cp_commit();

    // normalized accumulators -> SXA
    {
        const float i0 = 1.f / fmaxf(ds0, 1.f);
        const float i1 = 1.f / fmaxf(ds1, 1.f);
        const int rg = w * 16 + rl;
#pragma unroll
        for (int nt = 0; nt < 8; nt++) {
            int col = nt * 8 + 2 * t4;
            *(float2*)(SXA + rg * 68 + col) =
                make_float2(acc[nt][0] * i0, acc[nt][1] * i0);
            *(float2*)(SXA + (rg + 8) * 68 + col) =
                make_float2(acc[nt][2] * i1, acc[nt][3] * i1);
        }
    }
    cp_wait0();
    __syncthreads();

    // fp32 FFMA: thread (r = tid>>1, q = tid&1): q0 = self half, q1 = neigh half
    {
        const int r = tid >> 1, q = tid & 1;
        const float* src  = (q ? SXA : SXS) + r * 68;
        const float* W    = q ? WNN : WSS;
        const float* bias = q ? bn : bs;
        float* dst = out + (size_t)(row0 + r) * 128 + q * 64;
#pragma unroll
        for (int p = 0; p < 2; p++) {     // two 32-col passes
            float a[32];
#pragma unroll
            for (int j = 0; j < 32; j++) a[j] = 0.f;
#pragma unroll 4
            for (int k = 0; k < 64; k++) {
                float v = src[k];
                const float* wr = W + k * 64 + p * 32;
#pragma unroll
                for (int j = 0; j < 8; j++) {
                    float4 ww = *(const float4*)(wr + j * 4);
                    a[4*j]   += v * ww.x; a[4*j+1] += v * ww.y;
                    a[4*j+2] += v * ww.z; a[4*j+3] += v * ww.w;
                }
            }
#pragma unroll
            for (int j = 0; j < 8; j++) {
                float4 b = *(const float4*)(bias + p * 32 + j * 4);
                *(float4*)(dst + p * 32 + j * 4) =
                    make_float4(a[4*j] + b.x, a[4*j+1] + b.y,
                                a[4*j+2] + b.z, a[4*j+3] + b.w);
            }
        }
    }
}

// ---------------------------------------------------------------------------
extern "C" void kernel_launch(void* const* d_in, const int* in_sizes, int n_in,
                              void* d_out, int out_size)
{
    const float* self_x     = (const float*)d_in[0];
    const float* neighbor_x = (const float*)d_in[1];
    const float* adj        = (const float*)d_in[2];
    const float* Ws         = (const float*)d_in[3];
    const float* Wn         = (const float*)d_in[4];
    const float* bs         = (const float*)d_in[5];
    const float* bn         = (const float*)d_in[6];
    float* out = (float*)d_out;

    cudaFuncSetAttribute(agg_gemm, cudaFuncAttributeMaxDynamicSharedMemorySize, DSMEM);

    prep_b<<<NKT, 256>>>(neighbor_x);
    agg_gemm<<<Nn / BM, 128, DSMEM>>>(adj, self_x, Ws, Wn, bs, bn, out);
}